// round 3
// baseline (speedup 1.0000x reference)
#include <cuda_runtime.h>
#include <cuda_bf16.h>
#include <cstdint>
#include <cstddef>

// ============================================================================
// QLinear via int8 IMMA (mma.sync m16n8k32 s8.s8.s32) — exact integer math.
// w_s = max|W|/127; b_s = w_s*a_s; out = (x_int @ w_int^T + b_int) * b_s
// NOTE: harness PTX target is base sm_100 (no 'a') -> tcgen05 unavailable.
// ============================================================================

#define DEV_INLINE __device__ __forceinline__

namespace {
constexpr int NTOK = 32768;
constexpr int DIN  = 768;
constexpr int DOUT = 768;
constexpr long long NM = (long long)NTOK * DOUT;

constexpr int BM = 128;
constexpr int BN = 128;
constexpr int BK = 128;               // bytes of K per stage (int8)
constexpr int KT = DIN / BK;          // 6
constexpr int STAGES = 3;
constexpr int THREADS = 256;

constexpr int STRIDE = 144;           // 128B data + 16B pad: conflict-free ldmatrix
constexpr int A_BYTES = BM * STRIDE;  // 18432
constexpr int B_BYTES = BN * STRIDE;  // 18432
constexpr int STAGE_BYTES = A_BYTES + B_BYTES;        // 36864
constexpr int SMEM_BYTES  = STAGES * STAGE_BYTES;     // 110592
} // namespace

// ---------------- device scratch (static: no runtime allocation) ------------
__device__ __align__(16) int8_t g_xq[(size_t)NTOK * DIN]; // 25.2 MB
__device__ __align__(16) int8_t g_wq[(size_t)DOUT * DIN]; // 0.59 MB
__device__ __align__(16) float  g_bint[DOUT];
__device__ unsigned int g_wmax_bits;
__device__ float g_ws;
__device__ float g_bs;

// ---------------- PTX helpers ------------------------------------------------
DEV_INLINE uint32_t smem_u32(const void* p) {
    uint32_t a;
    asm("{ .reg .u64 t; cvta.to.shared.u64 t, %1; cvt.u32.u64 %0, t; }" : "=r"(a) : "l"(p));
    return a;
}

#define CP16(dst, src) \
    asm volatile("cp.async.cg.shared.global [%0], [%1], 16;" :: "r"(dst), "l"(src))
#define CP_COMMIT() asm volatile("cp.async.commit_group;" ::: "memory")
#define CP_WAIT(n)  asm volatile("cp.async.wait_group %0;" :: "n"(n) : "memory")

#define LDSM_X4(r, addr)                                                        \
    asm volatile("ldmatrix.sync.aligned.m8n8.x4.shared.b16 {%0,%1,%2,%3}, [%4];" \
        : "=r"((r)[0]), "=r"((r)[1]), "=r"((r)[2]), "=r"((r)[3]) : "r"(addr))

#define IMMA(d, a, b0, b1)                                                      \
    asm volatile("mma.sync.aligned.m16n8k32.row.col.s32.s8.s8.s32 "             \
        "{%0,%1,%2,%3}, {%4,%5,%6,%7}, {%8,%9}, {%0,%1,%2,%3};"                 \
        : "+r"((d)[0]), "+r"((d)[1]), "+r"((d)[2]), "+r"((d)[3])                \
        : "r"((a)[0]), "r"((a)[1]), "r"((a)[2]), "r"((a)[3]), "r"(b0), "r"(b1))

// ---------------- small kernels ----------------------------------------------
__global__ void qlinear_init() { g_wmax_bits = 0u; }

__global__ void qlinear_wmax(const float* __restrict__ w) {
    float m = 0.f;
    const float4* w4 = reinterpret_cast<const float4*>(w);
    int n4 = (DOUT * DIN) >> 2;
    for (int j = blockIdx.x * blockDim.x + threadIdx.x; j < n4; j += gridDim.x * blockDim.x) {
        float4 v = w4[j];
        m = fmaxf(m, fmaxf(fmaxf(fabsf(v.x), fabsf(v.y)), fmaxf(fabsf(v.z), fabsf(v.w))));
    }
    #pragma unroll
    for (int o = 16; o; o >>= 1) m = fmaxf(m, __shfl_xor_sync(0xffffffffu, m, o));
    if ((threadIdx.x & 31) == 0) atomicMax(&g_wmax_bits, __float_as_uint(m));
}

__global__ void qlinear_finalize(const float* __restrict__ a_s,
                                 float* __restrict__ out, long long out_size) {
    float ws = __fdiv_rn(__uint_as_float(g_wmax_bits), 127.0f);
    float bs = __fmul_rn(ws, a_s[0]);
    if (threadIdx.x == 0) { g_ws = ws; g_bs = bs; }
    for (long long i = NM + threadIdx.x; i < out_size; i += blockDim.x) out[i] = bs;
}

DEV_INLINE float q8f(float x, float s) {
    return fminf(fmaxf(rintf(__fdiv_rn(x, s)), -128.f), 127.f);
}
DEV_INLINE uint32_t pack4(float a, float b, float c, float d) {
    return (uint32_t)((int)a & 0xff) | ((uint32_t)((int)b & 0xff) << 8) |
           ((uint32_t)((int)c & 0xff) << 16) | ((uint32_t)((int)d & 0xff) << 24);
}

__global__ void qlinear_quant_w(const float* __restrict__ w) {
    const float ws = g_ws;
    const float4* w4 = reinterpret_cast<const float4*>(w);
    uint32_t* dst = reinterpret_cast<uint32_t*>(g_wq);
    int n4 = (DOUT * DIN) >> 2;
    for (int j = blockIdx.x * blockDim.x + threadIdx.x; j < n4; j += gridDim.x * blockDim.x) {
        float4 v = w4[j];
        dst[j] = pack4(q8f(v.x, ws), q8f(v.y, ws), q8f(v.z, ws), q8f(v.w, ws));
    }
}

__global__ void qlinear_quant_x(const float* __restrict__ x, const float* __restrict__ a_s) {
    const float s = a_s[0];
    const float4* x4 = reinterpret_cast<const float4*>(x);
    uint32_t* dst = reinterpret_cast<uint32_t*>(g_xq);
    int n4 = (NTOK * DIN) >> 2;
    for (int j = blockIdx.x * blockDim.x + threadIdx.x; j < n4; j += gridDim.x * blockDim.x) {
        float4 v = x4[j];
        dst[j] = pack4(q8f(v.x, s), q8f(v.y, s), q8f(v.z, s), q8f(v.w, s));
    }
}

__global__ void qlinear_quant_b(const float* __restrict__ bias) {
    int i = blockIdx.x * blockDim.x + threadIdx.x;
    if (i < DOUT) {
        float q = rintf(__fdiv_rn(bias[i], g_bs));
        g_bint[i] = fminf(fmaxf(q, -2147483648.f), 2147483648.f);
    }
}

// ---------------- GEMM -------------------------------------------------------
DEV_INLINE void load_stage(uint32_t sbase, const int8_t* gA, const int8_t* gB,
                           int kt, int tid) {
    const int kbase = kt * BK;
    #pragma unroll
    for (int j = 0; j < 4; j++) {          // A: 128 rows x 8 chunks of 16B
        int idx = tid + j * THREADS;
        int r = idx >> 3, c = idx & 7;
        CP16(sbase + r * STRIDE + c * 16, gA + (size_t)r * DIN + kbase + c * 16);
    }
    #pragma unroll
    for (int j = 0; j < 4; j++) {          // B: 128 rows x 8 chunks of 16B
        int idx = tid + j * THREADS;
        int r = idx >> 3, c = idx & 7;
        CP16(sbase + A_BYTES + r * STRIDE + c * 16, gB + (size_t)r * DIN + kbase + c * 16);
    }
    CP_COMMIT();
}

__global__ __launch_bounds__(THREADS, 1) void qlinear_gemm(float* __restrict__ out) {
    extern __shared__ char smem_raw[];
    const uint32_t sb = smem_u32(smem_raw);
    const int tid  = threadIdx.x;
    const int lane = tid & 31;
    const int wid  = tid >> 5;
    const int warp_m = wid & 3;            // 4 warps over M
    const int warp_n = wid >> 2;           // 2 warps over N
    const int m0 = blockIdx.y * BM;
    const int n0 = blockIdx.x * BN;

    const int8_t* gA = g_xq + (size_t)m0 * DIN;
    const int8_t* gB = g_wq + (size_t)n0 * DIN;

    // prologue
    load_stage(sb + 0 * STAGE_BYTES, gA, gB, 0, tid);
    load_stage(sb + 1 * STAGE_BYTES, gA, gB, 1, tid);

    int acc[2][8][4];
    #pragma unroll
    for (int mi = 0; mi < 2; mi++)
        #pragma unroll
        for (int na = 0; na < 8; na++)
            #pragma unroll
            for (int q = 0; q < 4; q++) acc[mi][na][q] = 0;

    // per-thread ldmatrix base offsets (row = lane&15, +16B half for lane>=16)
    const uint32_t lmA = (uint32_t)(warp_m * 32 + (lane & 15)) * STRIDE + (lane & 16);
    const uint32_t lmB = (uint32_t)(warp_n * 64 + (lane & 15)) * STRIDE + (lane & 16);

    for (int kt = 0; kt < KT; kt++) {
        const int slot = kt % STAGES;
        if (kt == KT - 1) { CP_WAIT(0); } else { CP_WAIT(1); }
        __syncthreads();

        if (kt + 2 < KT)
            load_stage(sb + ((kt + 2) % STAGES) * STAGE_BYTES, gA, gB, kt + 2, tid);

        const uint32_t aBase = sb + slot * STAGE_BYTES + lmA;
        const uint32_t bBase = sb + slot * STAGE_BYTES + A_BYTES + lmB;

        #pragma unroll
        for (int ks = 0; ks < 4; ks++) {   // 4 x k32 per 128B stage
            uint32_t af[2][4];
            #pragma unroll
            for (int mi = 0; mi < 2; mi++)
                LDSM_X4(af[mi], aBase + mi * 16 * STRIDE + ks * 32);
            uint32_t bf[4][4];
            #pragma unroll
            for (int nj = 0; nj < 4; nj++)
                LDSM_X4(bf[nj], bBase + nj * 16 * STRIDE + ks * 32);
            #pragma unroll
            for (int mi = 0; mi < 2; mi++)
                #pragma unroll
                for (int na = 0; na < 8; na++) {
                    const int nj = na >> 1, hi = na & 1;
                    IMMA(acc[mi][na], af[mi], bf[nj][hi], bf[nj][hi + 2]);
                }
        }
    }

    // epilogue: (acc + b_int) * b_s, direct float2 global stores (exact math)
    const float bs = g_bs;
    const int g = lane >> 2, tig = lane & 3;
    #pragma unroll
    for (int mi = 0; mi < 2; mi++) {
        #pragma unroll
        for (int na = 0; na < 8; na++) {
            const int row = m0 + warp_m * 32 + mi * 16 + g;
            const int col = n0 + warp_n * 64 + na * 8 + 2 * tig;
            const float2 bi = *reinterpret_cast<const float2*>(&g_bint[col]);
            float2 v0, v1;
            v0.x = (__int2float_rn(acc[mi][na][0]) + bi.x) * bs;
            v0.y = (__int2float_rn(acc[mi][na][1]) + bi.y) * bs;
            v1.x = (__int2float_rn(acc[mi][na][2]) + bi.x) * bs;
            v1.y = (__int2float_rn(acc[mi][na][3]) + bi.y) * bs;
            *reinterpret_cast<float2*>(&out[(size_t)row * DOUT + col]) = v0;
            *reinterpret_cast<float2*>(&out[(size_t)(row + 8) * DOUT + col]) = v1;
        }
    }
}

// ---------------- launch -----------------------------------------------------
extern "C" void kernel_launch(void* const* d_in, const int* in_sizes, int n_in,
                              void* d_out, int out_size) {
    const float *x = nullptr, *a_s = nullptr, *w = nullptr, *bias = nullptr;
    for (int i = 0; i < n_in; i++) {
        if      (in_sizes[i] == NTOK * DIN) x    = (const float*)d_in[i];
        else if (in_sizes[i] == 1)          a_s  = (const float*)d_in[i];
        else if (in_sizes[i] == DOUT * DIN) w    = (const float*)d_in[i];
        else if (in_sizes[i] == DOUT)       bias = (const float*)d_in[i];
    }
    float* out = (float*)d_out;

    cudaFuncSetAttribute(qlinear_gemm, cudaFuncAttributeMaxDynamicSharedMemorySize, SMEM_BYTES);

    qlinear_init<<<1, 1>>>();
    qlinear_wmax<<<1184, 256>>>(w);
    qlinear_finalize<<<1, 256>>>(a_s, out, (long long)out_size);
    qlinear_quant_w<<<576, 256>>>(w);
    qlinear_quant_b<<<3, 256>>>(bias);
    qlinear_quant_x<<<12288, 512>>>(x, a_s);

    dim3 grid(DOUT / BN, NTOK / BM);   // (6, 256) = 1536 CTAs
    qlinear_gemm<<<grid, THREADS, SMEM_BYTES>>>(out);
}